// round 10
// baseline (speedup 1.0000x reference)
#include <cuda_runtime.h>
#include <cstdint>
#include <cfloat>

// Problem constants
#define K_CODES 1024
#define DIM     256
#define BATCH   32
#define TLEN    2048
#define NROWS   (BATCH * TLEN)                 // 65536
#define QELEMS  ((size_t)BATCH * DIM * TLEN)   // 16777216
#define LOSS_OFF ((size_t)16777216)
#define IDX_OFF  ((size_t)16777217)

#define ROWS 128
#define THREADS 1024
#define KTILE  128
#define NTILES (K_CODES / KTILE)   // 8
#define RST 272                    // padded row stride in bytes (s8 tiles)
#define EH_BYTES (KTILE * RST)     // 34816 per buffer
#define SE 129024.0f               // e quantization scale (126*1024)

// Scratch (no allocations allowed)
__device__ float  g_emb_t[DIM * K_CODES];        // transposed codebook [d][k]
__device__ float  g_esq[K_CODES];                // ||e_k||^2 exact
__device__ signed char g_emb_i8[K_CODES * DIM];  // round(e * SE) [k][d]
__device__ double g_loss;

// Dynamic smem offsets (bytes)
#define OFF_A     0                 // [128 rows][272B] int8 quantized x
#define OFF_EH    34816             // 2 x [128 codes][272B] int8
#define OFF_ESQ   104448            // [1024] float (raw esq)
#define OFF_TMIN  108544            // [8][128] unsigned (encoded float)
#define OFF_MASK  112640            // [8][128][4] unsigned
#define OFF_WIN   129024            // [128] u64
#define OFF_XSQ   130048            // [128] float
#define OFF_MARG  130560            // [128] float (margin, key units)
#define OFF_GMIN  131072            // [128] float
#define OFF_SX    131584            // [128] float (per-row x scale)
#define OFF_BIDX  132096            // [128] int
#define SMEM_SZ   132608

__device__ __forceinline__ void imma16832(int c[4], const unsigned a[4], const unsigned b[2]) {
    asm volatile(
        "mma.sync.aligned.m16n8k32.row.col.s32.s8.s8.s32 "
        "{%0,%1,%2,%3}, {%4,%5,%6,%7}, {%8,%9}, {%0,%1,%2,%3};"
        : "+r"(c[0]), "+r"(c[1]), "+r"(c[2]), "+r"(c[3])
        : "r"(a[0]), "r"(a[1]), "r"(a[2]), "r"(a[3]), "r"(b[0]), "r"(b[1]));
}

__device__ __forceinline__ void ldsm_x4(unsigned r[4], const void* p) {
    unsigned addr = (unsigned)__cvta_generic_to_shared(p);
    asm volatile("ldmatrix.sync.aligned.m8n8.x4.shared.b16 {%0,%1,%2,%3}, [%4];"
                 : "=r"(r[0]), "=r"(r[1]), "=r"(r[2]), "=r"(r[3]) : "r"(addr));
}

__device__ __forceinline__ void cp_async16(unsigned dst, const void* src) {
    asm volatile("cp.async.cg.shared.global [%0], [%1], 16;"
                 :: "r"(dst), "l"(src) : "memory");
}

// monotone float<->unsigned map
__device__ __forceinline__ unsigned fenc(float f) {
    unsigned b = __float_as_uint(f);
    return b ^ ((unsigned)((int)b >> 31) | 0x80000000u);
}
__device__ __forceinline__ float fdec(unsigned u) {
    unsigned b = u ^ (((int)u >= 0) ? 0xFFFFFFFFu : 0x80000000u);
    return __uint_as_float(b);
}

// ---------------------------------------------------------------------------
// prep: transpose codebook, ||e||^2, int8 scaled codebook, zero loss
// ---------------------------------------------------------------------------
__global__ void vq_prep(const float* __restrict__ emb) {
    int k = blockIdx.x;
    int d = threadIdx.x;
    float v = emb[k * DIM + d];
    g_emb_t[(size_t)d * K_CODES + k] = v;
    int q = __float2int_rn(v * SE);
    q = max(-127, min(127, q));
    g_emb_i8[(size_t)k * DIM + d] = (signed char)q;

    __shared__ float red[DIM];
    red[d] = v * v;
    __syncthreads();
    #pragma unroll
    for (int s = DIM / 2; s > 0; s >>= 1) {
        if (d < s) red[d] += red[d + s];
        __syncthreads();
    }
    if (d == 0) g_esq[k] = red[0];
    if (k == 0 && d == 0) g_loss = 0.0;
}

// ---------------------------------------------------------------------------
// main: int8 IMMA approx (exact s32 accum) -> masks -> exact rescore -> epilogue
// grid: 512 blocks x 1024 threads, ~129.5KB dyn smem
// ---------------------------------------------------------------------------
__global__ void __launch_bounds__(THREADS)
vq_main(const float* __restrict__ x_in, const float* __restrict__ emb,
        float* __restrict__ out) {
    extern __shared__ char sm[];
    float*  esqs = (float*)(sm + OFF_ESQ);
    unsigned* tmin = (unsigned*)(sm + OFF_TMIN);
    unsigned* cmask = (unsigned*)(sm + OFF_MASK);
    unsigned long long* winner = (unsigned long long*)(sm + OFF_WIN);
    float*  xsqs = (float*)(sm + OFF_XSQ);
    float*  margA = (float*)(sm + OFF_MARG);
    float*  gmin = (float*)(sm + OFF_GMIN);
    float*  sxs  = (float*)(sm + OFF_SX);
    int*    bidx = (int*)(sm + OFF_BIDX);

    const unsigned smem_base = (unsigned)__cvta_generic_to_shared(sm);
    const int tid = threadIdx.x;
    const int blk = blockIdx.x;
    const int b   = blk >> 4;
    const int t0  = (blk & 15) * ROWS;
    const float* xbase = x_in + (size_t)b * DIM * TLEN + t0;

    // init scratch
    for (int i = tid; i < NTILES * ROWS; i += THREADS) tmin[i] = 0xFFFFFFFFu;
    for (int i = tid; i < NTILES * ROWS * 4; i += THREADS) cmask[i] = 0u;
    if (tid < ROWS) winner[tid] = ~0ull;
    for (int i = tid; i < K_CODES; i += THREADS) esqs[i] = g_esq[i];

    // prefetch E tile 0 (32KB = 2048 x 16B)
    {
        const char* srcb = (const char*)g_emb_i8;
        #pragma unroll
        for (int l = 0; l < 2; ++l) {
            int idx = tid + l * THREADS;
            int code = idx >> 4, j = idx & 15;
            cp_async16(smem_base + OFF_EH + code * RST + j * 16,
                       srcb + code * 256 + j * 16);
        }
        asm volatile("cp.async.commit_group;" ::: "memory");
    }

    // per-row: ||x||^2 (exact chain), sum|x|, max|x| -> sx, margin (key units)
    if (tid < ROWS) {
        float s = 0.f, sa = 0.f, mx = 0.f;
        #pragma unroll 8
        for (int d = 0; d < DIM; ++d) {
            float v = xbase[(size_t)d * TLEN + tid];
            s = __fmaf_rn(v, v, s);
            sa += fabsf(v);
            mx = fmaxf(mx, fabsf(v));
        }
        xsqs[tid] = s;
        float sx = 126.0f / fmaxf(mx, 1e-20f);
        sxs[tid] = sx;
        // sound dot-error bound (dist units):
        //   err <= (0.5/SE)(sa + 128/sx) + 0.125/sx + 64/(sx*SE)
        float err = (0.5f / SE) * (sa + 128.0f / sx)
                  + 0.125f / sx + 64.0f / (sx * SE);
        // key = (sx*SE/2)*(esq - 2*dot_apx); margin in key units
        margA[tid] = (0.5f * sx * SE) * (2.0f * err + 3e-4f);
    }
    __syncthreads();

    // A tile: per-row int8 quantize, 4 packed per int32 (coalesced along r)
    for (int i = tid; i < 64 * ROWS; i += THREADS) {
        int d4 = i >> 7, r = i & 127;
        float sx = sxs[r];
        unsigned pk = 0u;
        #pragma unroll
        for (int u = 0; u < 4; ++u) {
            int q = __float2int_rn(xbase[(size_t)(4 * d4 + u) * TLEN + r] * sx);
            q = max(-127, min(127, q));
            pk |= ((unsigned)q & 0xFFu) << (8 * u);
        }
        *(unsigned*)(sm + OFF_A + r * RST + d4 * 4) = pk;
    }
    __syncthreads();

    const int lane = tid & 31, w = tid >> 5;
    const int g = lane >> 2, tk2 = lane & 3;
    const int r0 = (w & 7) * 16;   // warp's 16 rows
    const int c0 = (w >> 3) * 32;  // warp's 32 codes within 128-code tile

    for (int kt = 0; kt < NTILES; ++kt) {
        asm volatile("cp.async.wait_group 0;" ::: "memory");
        __syncthreads();   // tile kt staged; all warps done reading tile kt-1

        // prefetch tile kt+1 (overlaps this tile's MMA)
        if (kt + 1 < NTILES) {
            const char* srcb = (const char*)g_emb_i8 + (size_t)(kt + 1) * KTILE * DIM;
            unsigned dbase = smem_base + OFF_EH + ((kt + 1) & 1) * EH_BYTES;
            #pragma unroll
            for (int l = 0; l < 2; ++l) {
                int idx = tid + l * THREADS;
                int code = idx >> 4, j = idx & 15;
                cp_async16(dbase + code * RST + j * 16, srcb + code * 256 + j * 16);
            }
            asm volatile("cp.async.commit_group;" ::: "memory");
        }

        const char* EhT = sm + OFF_EH + (kt & 1) * EH_BYTES;

        int acc[4][4];
        #pragma unroll
        for (int nn = 0; nn < 4; ++nn)
            #pragma unroll
            for (int c = 0; c < 4; ++c) acc[nn][c] = 0;

        #pragma unroll
        for (int kb = 0; kb < 8; ++kb) {     // 8 k-steps of 32 bytes
            const int kbB = kb * 32;
            unsigned a[4], bf[4][2];
            {
                int rowA = r0 + (lane & 15);
                ldsm_x4(a, sm + OFF_A + rowA * RST + kbB + (lane & 16));
            }
            #pragma unroll
            for (int nn2 = 0; nn2 < 2; ++nn2) {
                int nrow = c0 + nn2 * 16 + (lane & 7) + ((lane & 16) >> 1);
                unsigned r4[4];
                ldsm_x4(r4, EhT + nrow * RST + kbB + 2 * (lane & 8));
                bf[2 * nn2][0] = r4[0]; bf[2 * nn2][1] = r4[1];
                bf[2 * nn2 + 1][0] = r4[2]; bf[2 * nn2 + 1][1] = r4[3];
            }
            #pragma unroll
            for (int nn = 0; nn < 4; ++nn)
                imma16832(acc[nn], a, bf[nn]);
        }

        // pass 1: key = (sx*SE/2)*esq - acc (int->float exact, |acc|<2^24)
        float sh[2] = { sxs[r0 + g] * (0.5f * SE), sxs[r0 + g + 8] * (0.5f * SE) };
        float sq[8];
        #pragma unroll
        for (int nn = 0; nn < 4; ++nn) {
            sq[nn * 2]     = esqs[kt * KTILE + c0 + nn * 8 + 2 * tk2];
            sq[nn * 2 + 1] = esqs[kt * KTILE + c0 + nn * 8 + 2 * tk2 + 1];
        }
        float dv[4][4];
        float rmin[2] = {FLT_MAX, FLT_MAX};
        #pragma unroll
        for (int nn = 0; nn < 4; ++nn)
            #pragma unroll
            for (int c = 0; c < 4; ++c) {
                int ch = c >> 1;
                float d = __fmaf_rn(sh[ch], sq[nn * 2 + (c & 1)],
                                    -__int2float_rn(acc[nn][c]));
                dv[nn][c] = d;
                rmin[ch] = fminf(rmin[ch], d);
            }
        #pragma unroll
        for (int ch = 0; ch < 2; ++ch) {
            float v = rmin[ch];
            v = fminf(v, __shfl_xor_sync(0xffffffffu, v, 1));
            v = fminf(v, __shfl_xor_sync(0xffffffffu, v, 2));
            if (tk2 == 0)
                atomicMin(&tmin[kt * ROWS + r0 + g + ch * 8], fenc(v));
        }
        __syncthreads();

        // pass 2: flag candidates within margin of tile-min
        float lim[2];
        #pragma unroll
        for (int ch = 0; ch < 2; ++ch) {
            int row = r0 + g + ch * 8;
            lim[ch] = fdec(tmin[kt * ROWS + row]) + margA[row];
        }
        #pragma unroll
        for (int nn = 0; nn < 4; ++nn)
            #pragma unroll
            for (int c = 0; c < 4; ++c) {
                if (dv[nn][c] <= lim[c >> 1]) {
                    int kloc = c0 + nn * 8 + 2 * tk2 + (c & 1);
                    int row  = r0 + g + (c >> 1) * 8;
                    atomicOr(&cmask[(kt * ROWS + row) * 4 + (kloc >> 5)],
                             1u << (kloc & 31));
                }
            }
    }
    __syncthreads();

    // global approx min per row (key units, per-row consistent)
    if (tid < ROWS) {
        float m = FLT_MAX;
        #pragma unroll
        for (int t = 0; t < NTILES; ++t)
            m = fminf(m, fdec(tmin[t * ROWS + tid]));
        gmin[tid] = m;
    }
    __syncthreads();

    // exact rescore of candidates (identical fp32 fma chain as rounds 1-9)
    for (int p = tid; p < ROWS * NTILES; p += THREADS) {
        int r = p >> 3, t = p & 7;
        if (fdec(tmin[t * ROWS + r]) <= gmin[r] + margA[r]) {
            #pragma unroll
            for (int w4 = 0; w4 < 4; ++w4) {
                unsigned m = cmask[(t * ROWS + r) * 4 + w4];
                while (m) {
                    int bit = __ffs(m) - 1; m &= m - 1;
                    int k = t * KTILE + w4 * 32 + bit;
                    const float* ek = emb + (size_t)k * DIM;
                    float accv = 0.f;
                    #pragma unroll 8
                    for (int d = 0; d < DIM; ++d)
                        accv = __fmaf_rn(xbase[(size_t)d * TLEN + r], ek[d], accv);
                    float dd = __fsub_rn(__fadd_rn(xsqs[r], g_esq[k]),
                                         __fmul_rn(2.0f, accv));
                    unsigned long long key =
                        ((unsigned long long)__float_as_uint(dd) << 32) | (unsigned)k;
                    atomicMin(&winner[r], key);
                }
            }
        }
    }
    __syncthreads();

    if (tid < ROWS) {
        int bi = (int)(winner[tid] & 0xffffffffu);
        bidx[tid] = bi;
        out[IDX_OFF + (size_t)b * TLEN + t0 + tid] = (float)bi;
    }
    __syncthreads();

    // quantized output (straight-through, reference rounding) + loss partial
    double lsum = 0.0;
    #pragma unroll 2
    for (int i = tid; i < DIM * ROWS; i += THREADS) {
        int d = i >> 7, r = i & 127;
        float q = g_emb_t[(size_t)d * K_CODES + bidx[r]];
        float x = xbase[(size_t)d * TLEN + r];
        float diff = __fsub_rn(q, x);
        lsum += (double)diff * (double)diff;
        out[(size_t)b * DIM * TLEN + (size_t)d * TLEN + t0 + r] = __fadd_rn(x, diff);
    }
    #pragma unroll
    for (int o = 16; o > 0; o >>= 1)
        lsum += __shfl_down_sync(0xffffffffu, lsum, o);
    __shared__ double lred[32];
    if ((tid & 31) == 0) lred[tid >> 5] = lsum;
    __syncthreads();
    if (tid == 0) {
        double s = 0.0;
        #pragma unroll
        for (int wv = 0; wv < 32; ++wv) s += lred[wv];
        atomicAdd(&g_loss, s);
    }
}

// ---------------------------------------------------------------------------
__global__ void vq_finalize(float* __restrict__ out) {
    out[LOSS_OFF] = (float)(g_loss * 1.25 / (double)QELEMS);
}

// ---------------------------------------------------------------------------
extern "C" void kernel_launch(void* const* d_in, const int* in_sizes, int n_in,
                              void* d_out, int out_size) {
    const float* x_in = (const float*)d_in[0];   // [B, D, T] float32
    const float* emb  = (const float*)d_in[1];   // [K, D]    float32
    float* out = (float*)d_out;

    static int smem_set = 0;
    if (!smem_set) {
        cudaFuncSetAttribute(vq_main, cudaFuncAttributeMaxDynamicSharedMemorySize,
                             SMEM_SZ);
        smem_set = 1;
    }

    vq_prep<<<K_CODES, DIM>>>(emb);
    vq_main<<<NROWS / ROWS, THREADS, SMEM_SZ>>>(x_in, emb, out);
    vq_finalize<<<1, 1>>>(out);
}